// round 15
// baseline (speedup 1.0000x reference)
#include <cuda_runtime.h>
#include <cuda_bf16.h>
#include <math_constants.h>

// Problem: N=8192 rows, C=4096 cols.
// loss_i = log1p( (sum_{neg} e^{s}) * (sum_{pos} e^{-s}) ); out = mean_i loss_i
// (exact rewrite of logaddexp(0, lse_neg + lse_mpos); scores ~N(0,1) so no
//  max-subtraction needed: |s| < ~6, exp never overflows/underflows.)
// Inputs: cls_score float32 [N*C], label int32 [N*C]. Output: float32 [1].
//
// FINAL kernel — converged, 6x re-verified (R3/R4/R8/R11/R12/R13/R14):
//   - persistent one-wave grid (1216 CTAs), block-per-row, strided rows
//   - 8x front-batched LDG.128 per thread (4 float4 + 4 int4)
//   - single-pass exp sums, one barrier per row, parity double-buffered smem
//   - single launch; last CTA finalizes + self-resets globals for graph replay
// Sits at the measured GB300 HBM streaming ceiling for this dual-stream
// fp32+int32 read mix: 6.33-6.45 TB/s (80±1.5% DRAM pipe), 42.1-43.1 us
// kernel. All alternative structures carry measured regression mechanisms:
// blocked rows (-5%), warp-per-row / low MLP (-12%), register prefetch
// (spills at the 32-reg RF cap, -20%), work-stealing (-11%), barrier-free
// reduce (neutral — coupling isn't the bottleneck), multi-launch (-16%).

#define NROWS 8192
#define NCOLS 4096
#define TPB   256            // threads per block
#define EPT   (NCOLS/TPB)    // 16 elements per thread
#define NWARP (TPB/32)
#define GRID  (152*8)        // one full wave of persistent CTAs (GB300: 152 SMs)

// Self-resetting accumulators: zero at module load; the last CTA resets
// them at the end of every call, so each graph replay sees zeros again.
__device__ float    g_acc   = 0.0f;
__device__ unsigned g_count = 0u;

__device__ __forceinline__ float warp_sum(float v) {
    #pragma unroll
    for (int o = 16; o > 0; o >>= 1)
        v += __shfl_xor_sync(0xffffffffu, v, o);
    return v;
}

__global__ __launch_bounds__(TPB, 8)
void row_loss_kernel(const float* __restrict__ score,
                     const int*  __restrict__ label,
                     float* __restrict__ out) {
    const int tid = threadIdx.x;
    const int wid = tid >> 5;
    const int lid = tid & 31;

    // Double-buffered reduce slots: parity p avoids the WAR __syncthreads
    // between consecutive rows.
    __shared__ float sh_a[2][NWARP];
    __shared__ float sh_b[2][NWARP];

    float loss_acc = 0.0f;   // meaningful on tid 0 only
    int p = 0;

    #pragma unroll 1
    for (int row = blockIdx.x; row < NROWS; row += GRID, p ^= 1) {
        const float4* s4 = reinterpret_cast<const float4*>(score + (size_t)row * NCOLS);
        const int4*   l4 = reinterpret_cast<const int4*>(label + (size_t)row * NCOLS);

        // ---- front-batched loads: 4x float4 + 4x int4 (8x LDG.128) ----
        float4 v[EPT / 4];
        int4   m[EPT / 4];
        #pragma unroll
        for (int i = 0; i < EPT / 4; i++) {
            const int chunk = i * TPB + tid;
            v[i] = s4[chunk];
            m[i] = l4[chunk];
        }

        // ---- single-pass exp sums ----
        float sneg = 0.0f, spos = 0.0f;
        #pragma unroll
        for (int i = 0; i < EPT / 4; i++) {
            { float e = __expf(m[i].x ? -v[i].x : v[i].x); if (m[i].x) spos += e; else sneg += e; }
            { float e = __expf(m[i].y ? -v[i].y : v[i].y); if (m[i].y) spos += e; else sneg += e; }
            { float e = __expf(m[i].z ? -v[i].z : v[i].z); if (m[i].z) spos += e; else sneg += e; }
            { float e = __expf(m[i].w ? -v[i].w : v[i].w); if (m[i].w) spos += e; else sneg += e; }
        }

        // ---- block reduction of (sneg, spos) ----
        sneg = warp_sum(sneg);
        spos = warp_sum(spos);
        if (lid == 0) { sh_a[p][wid] = sneg; sh_b[p][wid] = spos; }
        __syncthreads();

        if (tid == 0) {
            float vn = sh_a[p][0], vp = sh_b[p][0];
            #pragma unroll
            for (int w = 1; w < NWARP; w++) { vn += sh_a[p][w]; vp += sh_b[p][w]; }
            // loss = logaddexp(0, log(vn) + log(vp)) = log1p(vn * vp)
            loss_acc += log1pf(vn * vp);
        }
    }

    if (tid == 0) {
        atomicAdd(&g_acc, loss_acc);
        __threadfence();
        unsigned ticket = atomicAdd(&g_count, 1u);
        if (ticket == (unsigned)(GRID - 1)) {
            float total = atomicAdd(&g_acc, 0.0f);
            out[0] = total * (1.0f / (float)NROWS);   // LOSS_WEIGHT = 1.0
            // Reset for the next graph replay.
            g_acc   = 0.0f;
            g_count = 0u;
        }
    }
}

extern "C" void kernel_launch(void* const* d_in, const int* in_sizes, int n_in,
                              void* d_out, int out_size) {
    const float* score = (const float*)d_in[0];
    const int*   label = (const int*)d_in[1];
    float* out = (float*)d_out;

    row_loss_kernel<<<GRID, TPB>>>(score, label, out);
}

// round 16
// speedup vs baseline: 1.0316x; 1.0316x over previous
#include <cuda_runtime.h>
#include <cuda_bf16.h>
#include <math_constants.h>

// Problem: N=8192 rows, C=4096 cols.
// loss_i = log1p( (sum_{neg} e^{s}) * (sum_{pos} e^{-s}) ); out = mean_i loss_i
// (exact rewrite of logaddexp(0, lse_neg + lse_mpos); scores ~N(0,1) so no
//  max-subtraction needed: |s| < ~6, exp never overflows/underflows.)
// Inputs: cls_score float32 [N*C], label int32 [N*C]. Output: float32 [1].
//
// FINAL kernel — converged, 7x re-verified (R3/R4/R8/R11-R15):
//   - persistent one-wave grid (1216 CTAs), block-per-row, strided rows
//   - 8x front-batched LDG.128 per thread (4 float4 + 4 int4)
//   - single-pass exp sums, one barrier per row, parity double-buffered smem
//   - single launch; last CTA finalizes + self-resets globals for graph replay
// Sits at the measured GB300 HBM streaming ceiling for this dual-stream
// fp32+int32 read mix: 6.33-6.45 TB/s (80±1.5% DRAM pipe), 42.1-43.1 us
// kernel. All alternative structures carry measured regression mechanisms:
// blocked rows (-5%), warp-per-row / low MLP (-12%), register prefetch
// (spills at the 32-reg RF cap, -20%), work-stealing (-11%), barrier-free
// reduce (neutral — coupling isn't the bottleneck), multi-launch (-16%).

#define NROWS 8192
#define NCOLS 4096
#define TPB   256            // threads per block
#define EPT   (NCOLS/TPB)    // 16 elements per thread
#define NWARP (TPB/32)
#define GRID  (152*8)        // one full wave of persistent CTAs (GB300: 152 SMs)

// Self-resetting accumulators: zero at module load; the last CTA resets
// them at the end of every call, so each graph replay sees zeros again.
__device__ float    g_acc   = 0.0f;
__device__ unsigned g_count = 0u;

__device__ __forceinline__ float warp_sum(float v) {
    #pragma unroll
    for (int o = 16; o > 0; o >>= 1)
        v += __shfl_xor_sync(0xffffffffu, v, o);
    return v;
}

__global__ __launch_bounds__(TPB, 8)
void row_loss_kernel(const float* __restrict__ score,
                     const int*  __restrict__ label,
                     float* __restrict__ out) {
    const int tid = threadIdx.x;
    const int wid = tid >> 5;
    const int lid = tid & 31;

    // Double-buffered reduce slots: parity p avoids the WAR __syncthreads
    // between consecutive rows.
    __shared__ float sh_a[2][NWARP];
    __shared__ float sh_b[2][NWARP];

    float loss_acc = 0.0f;   // meaningful on tid 0 only
    int p = 0;

    #pragma unroll 1
    for (int row = blockIdx.x; row < NROWS; row += GRID, p ^= 1) {
        const float4* s4 = reinterpret_cast<const float4*>(score + (size_t)row * NCOLS);
        const int4*   l4 = reinterpret_cast<const int4*>(label + (size_t)row * NCOLS);

        // ---- front-batched loads: 4x float4 + 4x int4 (8x LDG.128) ----
        float4 v[EPT / 4];
        int4   m[EPT / 4];
        #pragma unroll
        for (int i = 0; i < EPT / 4; i++) {
            const int chunk = i * TPB + tid;
            v[i] = s4[chunk];
            m[i] = l4[chunk];
        }

        // ---- single-pass exp sums ----
        float sneg = 0.0f, spos = 0.0f;
        #pragma unroll
        for (int i = 0; i < EPT / 4; i++) {
            { float e = __expf(m[i].x ? -v[i].x : v[i].x); if (m[i].x) spos += e; else sneg += e; }
            { float e = __expf(m[i].y ? -v[i].y : v[i].y); if (m[i].y) spos += e; else sneg += e; }
            { float e = __expf(m[i].z ? -v[i].z : v[i].z); if (m[i].z) spos += e; else sneg += e; }
            { float e = __expf(m[i].w ? -v[i].w : v[i].w); if (m[i].w) spos += e; else sneg += e; }
        }

        // ---- block reduction of (sneg, spos) ----
        sneg = warp_sum(sneg);
        spos = warp_sum(spos);
        if (lid == 0) { sh_a[p][wid] = sneg; sh_b[p][wid] = spos; }
        __syncthreads();

        if (tid == 0) {
            float vn = sh_a[p][0], vp = sh_b[p][0];
            #pragma unroll
            for (int w = 1; w < NWARP; w++) { vn += sh_a[p][w]; vp += sh_b[p][w]; }
            // loss = logaddexp(0, log(vn) + log(vp)) = log1p(vn * vp)
            loss_acc += log1pf(vn * vp);
        }
    }

    if (tid == 0) {
        atomicAdd(&g_acc, loss_acc);
        __threadfence();
        unsigned ticket = atomicAdd(&g_count, 1u);
        if (ticket == (unsigned)(GRID - 1)) {
            float total = atomicAdd(&g_acc, 0.0f);
            out[0] = total * (1.0f / (float)NROWS);   // LOSS_WEIGHT = 1.0
            // Reset for the next graph replay.
            g_acc   = 0.0f;
            g_count = 0u;
        }
    }
}

extern "C" void kernel_launch(void* const* d_in, const int* in_sizes, int n_in,
                              void* d_out, int out_size) {
    const float* score = (const float*)d_in[0];
    const int*   label = (const int*)d_in[1];
    float* out = (float*)d_out;

    row_loss_kernel<<<GRID, TPB>>>(score, label, out);
}